// round 7
// baseline (speedup 1.0000x reference)
#include <cuda_runtime.h>
#include <cuda_fp16.h>
#include <cstdint>

#define N_NODES 50000
#define D_FEAT  128
#define N_EDGES 800000

// Scratch (__device__ globals — allocation-free rule)
__device__ uint4  g_xh[N_NODES * 16];       // 12.8 MB fp16(x), unscaled
__device__ uint4  g_ph[N_NODES * 16];       // 12.8 MB fp16 pooled
__device__ int    g_hist_out[N_NODES];
__device__ int    g_hist_in[N_NODES];
__device__ int    g_start[N_NODES];
__device__ int    g_cursor[N_NODES];
__device__ int    g_sorted_src[N_EDGES];
__device__ float  g_sscale[N_NODES];
__device__ int    g_counter;

// ---------------------------------------------------------------------------
// K0: zero histograms + counter (vectorized)
// ---------------------------------------------------------------------------
__global__ void zero_kernel() {
    int i = blockIdx.x * blockDim.x + threadIdx.x;
    const int N4 = (N_NODES + 3) / 4;       // 12500
    int stride = gridDim.x * blockDim.x;
    for (int j = i; j < N4; j += stride) {
        reinterpret_cast<int4*>(g_hist_out)[j] = make_int4(0, 0, 0, 0);
        reinterpret_cast<int4*>(g_hist_in)[j]  = make_int4(0, 0, 0, 0);
    }
    if (i == 0) g_counter = 0;
}

// ---------------------------------------------------------------------------
// K1 FUSED: hist (8 edges/thread) + convert x->fp16 (no scale — independent).
// Hist blocks first (critical path for chunk); DRAM-bound convert overlaps.
// ---------------------------------------------------------------------------
#define HIST_T    (N_EDGES / 8)                      // 100000 threads
#define HIST_BLKS ((HIST_T + 255) / 256)             // 391
#define CONV_T    (N_NODES * 16 / 2)                 // 400000 threads
#define CONV_BLKS ((CONV_T + 255) / 256)             // 1563

__global__ __launch_bounds__(256) void histconv_kernel(
        const int* __restrict__ src,
        const int* __restrict__ tgt,
        const float4* __restrict__ x) {
    if (blockIdx.x < HIST_BLKS) {
        int t = blockIdx.x * 256 + threadIdx.x;
        if (t >= HIST_T) return;
        int sv[8], tg[8];
#pragma unroll
        for (int u = 0; u < 8; u++) {
            sv[u] = __ldg(&src[t + u * HIST_T]);
            tg[u] = __ldg(&tgt[t + u * HIST_T]);
        }
#pragma unroll
        for (int u = 0; u < 8; u++) atomicAdd(&g_hist_out[sv[u]], 1);
#pragma unroll
        for (int u = 0; u < 8; u++) atomicAdd(&g_hist_in[tg[u]], 1);
    } else {
        int i = (blockIdx.x - HIST_BLKS) * 256 + threadIdx.x;
        if (i >= CONV_T) return;
#pragma unroll
        for (int u = 0; u < 2; u++) {
            int idx = i + u * CONV_T;              // uint4 index (8 halfs)
            float4 v0 = __ldg(&x[2 * idx]);
            float4 v1 = __ldg(&x[2 * idx + 1]);
            __half2 h0 = __floats2half2_rn(v0.x, v0.y);
            __half2 h1 = __floats2half2_rn(v0.z, v0.w);
            __half2 h2 = __floats2half2_rn(v1.x, v1.y);
            __half2 h3 = __floats2half2_rn(v1.z, v1.w);
            uint4 p;
            p.x = *reinterpret_cast<uint32_t*>(&h0);
            p.y = *reinterpret_cast<uint32_t*>(&h1);
            p.z = *reinterpret_cast<uint32_t*>(&h2);
            p.w = *reinterpret_cast<uint32_t*>(&h3);
            g_xh[idx] = p;
        }
    }
}

// ---------------------------------------------------------------------------
// K2: chunk assignment (warp-aggregated global counter; order irrelevant)
// ---------------------------------------------------------------------------
__global__ void chunk_kernel() {
    int i    = blockIdx.x * blockDim.x + threadIdx.x;
    int lane = threadIdx.x & 31;
    int deg  = (i < N_NODES) ? g_hist_in[i] : 0;

    int incl = deg;
#pragma unroll
    for (int o = 1; o < 32; o <<= 1) {
        int n = __shfl_up_sync(0xFFFFFFFFu, incl, o);
        if (lane >= o) incl += n;
    }
    int total = __shfl_sync(0xFFFFFFFFu, incl, 31);
    int base = 0;
    if (lane == 31) base = atomicAdd(&g_counter, total);
    base = __shfl_sync(0xFFFFFFFFu, base, 31);

    if (i < N_NODES) {
        int st = base + incl - deg;
        g_start[i]  = st;
        g_cursor[i] = st;
        g_sscale[i] = rsqrtf(fmaxf((float)g_hist_out[i], 1.0f));
    }
}

// ---------------------------------------------------------------------------
// K3: counting-sort scatter, 16 independent edges per thread (MLP=16)
// ---------------------------------------------------------------------------
#define SORT_T (N_EDGES / 16)                        // 50000 threads

__global__ __launch_bounds__(256) void sort_kernel(
        const int* __restrict__ src,
        const int* __restrict__ tgt) {
    int t = blockIdx.x * 256 + threadIdx.x;
    if (t >= SORT_T) return;
    int tg[16], sv[16], p[16];
#pragma unroll
    for (int u = 0; u < 16; u++) {
        tg[u] = __ldg(&tgt[t + u * SORT_T]);
        sv[u] = __ldg(&src[t + u * SORT_T]);
    }
#pragma unroll
    for (int u = 0; u < 16; u++) p[u] = atomicAdd(&g_cursor[tg[u]], 1);
#pragma unroll
    for (int u = 0; u < 16; u++) g_sorted_src[p[u]] = sv[u];
}

// ---------------------------------------------------------------------------
// K4: gather. One warp per target node; half-warp per edge row (lane owns
// uint4 = 8 halfs) -> 2 edges/iter. Sender scale applied per edge (FMA);
// fp32 accumulate, shfl-combine halves, fp16 row written once.
// ---------------------------------------------------------------------------
__global__ __launch_bounds__(256) void gather_kernel() {
    int t    = (blockIdx.x * blockDim.x + threadIdx.x) >> 5;
    int lane = threadIdx.x & 31;
    if (t >= N_NODES) return;

    const int half = lane >> 4;    // which edge of the pair
    const int fl   = lane & 15;    // feature slot (8 halfs)

    int start = __ldg(&g_start[t]);
    int deg   = __ldg(&g_hist_in[t]);
    int end   = start + deg;

    float acc[8];
#pragma unroll
    for (int f = 0; f < 8; f++) acc[f] = 0.f;

    int j = start;
#pragma unroll 2
    for (; j + 1 < end; j += 2) {
        int   s  = __ldg(&g_sorted_src[j + half]);
        float sc = __ldg(&g_sscale[s]);
        uint4 e  = __ldg(&g_xh[s * 16 + fl]);
        const __half2* h = reinterpret_cast<const __half2*>(&e);
#pragma unroll
        for (int q = 0; q < 4; q++) {
            float2 f2 = __half22float2(h[q]);
            acc[2 * q]     = fmaf(sc, f2.x, acc[2 * q]);
            acc[2 * q + 1] = fmaf(sc, f2.y, acc[2 * q + 1]);
        }
    }
    if (j < end && half == 0) {    // odd tail: half 0 only
        int   s  = __ldg(&g_sorted_src[j]);
        float sc = __ldg(&g_sscale[s]);
        uint4 e  = __ldg(&g_xh[s * 16 + fl]);
        const __half2* h = reinterpret_cast<const __half2*>(&e);
#pragma unroll
        for (int q = 0; q < 4; q++) {
            float2 f2 = __half22float2(h[q]);
            acc[2 * q]     = fmaf(sc, f2.x, acc[2 * q]);
            acc[2 * q + 1] = fmaf(sc, f2.y, acc[2 * q + 1]);
        }
    }

#pragma unroll
    for (int f = 0; f < 8; f++)
        acc[f] += __shfl_down_sync(0xFFFFFFFFu, acc[f], 16);

    if (half == 0) {
        float rsc = rsqrtf(fmaxf((float)deg, 1.0f));
        __half2 h0 = __floats2half2_rn(acc[0] * rsc, acc[1] * rsc);
        __half2 h1 = __floats2half2_rn(acc[2] * rsc, acc[3] * rsc);
        __half2 h2 = __floats2half2_rn(acc[4] * rsc, acc[5] * rsc);
        __half2 h3 = __floats2half2_rn(acc[6] * rsc, acc[7] * rsc);
        uint4 p;
        p.x = *reinterpret_cast<uint32_t*>(&h0);
        p.y = *reinterpret_cast<uint32_t*>(&h1);
        p.z = *reinterpret_cast<uint32_t*>(&h2);
        p.w = *reinterpret_cast<uint32_t*>(&h3);
        g_ph[t * 16 + fl] = p;
    }
}

// ---------------------------------------------------------------------------
// K5: out = relu( pooled @ W + b ), fp16 mma.m16n8k16, fp32 accumulate.
// 256 thr, 128x128 tile, K=128 smem-resident, warp tile 32x64.
// ---------------------------------------------------------------------------
#define AS_U 68
#define WT_U 68
#define GEMM_SMEM ((128 * AS_U + 128 * WT_U) * 4)

#define MMA_F16(c, a, b)                                                      \
    asm volatile(                                                             \
        "mma.sync.aligned.m16n8k16.row.col.f32.f16.f16.f32 "                  \
        "{%0,%1,%2,%3},{%4,%5,%6,%7},{%8,%9},{%0,%1,%2,%3};"                  \
        : "+f"(c[0]), "+f"(c[1]), "+f"(c[2]), "+f"(c[3])                      \
        : "r"(a[0]), "r"(a[1]), "r"(a[2]), "r"(a[3]), "r"(b[0]), "r"(b[1]))

__global__ __launch_bounds__(256, 2) void gemm_kernel(
        const float4* __restrict__ W4,    // [128][32] float4 (k, j/4)
        const float*  __restrict__ bias,  // [128]
        float2* __restrict__ out2) {      // [N_NODES][64]
    extern __shared__ uint32_t smemU[];
    uint32_t* AsU = smemU;                 // [128][AS_U] half2 (row, k/2)
    uint32_t* WtU = smemU + 128 * AS_U;    // [128][WT_U] half2 (n,  k/2)
    __half*   WtH = reinterpret_cast<__half*>(WtU);

    const int tid  = threadIdx.x;
    const int lane = tid & 31;
    const int w    = tid >> 5;
    const int quad = lane >> 2;
    const int tq   = lane & 3;
    const int wr   = w & 3;
    const int wc   = w >> 2;
    const int rowBase = blockIdx.x * 128;

#pragma unroll
    for (int p = 0; p < 8; p++) {
        int idx = p * 256 + tid;          // 0..2047
        int r = idx >> 4, c = idx & 15;
        uint4 v = make_uint4(0u, 0u, 0u, 0u);
        if (rowBase + r < N_NODES) v = g_ph[(rowBase + r) * 16 + c];
        *reinterpret_cast<uint4*>(&AsU[r * AS_U + c * 4]) = v;
    }
#pragma unroll
    for (int p = 0; p < 16; p++) {
        int idx = p * 256 + tid;          // 0..4095
        int k = idx >> 5, c = idx & 31;
        float4 v = __ldg(&W4[idx]);
        WtH[(4 * c + 0) * (2 * WT_U) + k] = __float2half_rn(v.x);
        WtH[(4 * c + 1) * (2 * WT_U) + k] = __float2half_rn(v.y);
        WtH[(4 * c + 2) * (2 * WT_U) + k] = __float2half_rn(v.z);
        WtH[(4 * c + 3) * (2 * WT_U) + k] = __float2half_rn(v.w);
    }
    __syncthreads();

    float acc[2][8][4];
#pragma unroll
    for (int s = 0; s < 2; s++)
#pragma unroll
        for (int nt = 0; nt < 8; nt++)
#pragma unroll
            for (int j = 0; j < 4; j++) acc[s][nt][j] = 0.f;

#pragma unroll
    for (int kt = 0; kt < 8; kt++) {
        const int ko = kt * 8;
        uint32_t a[2][4];
#pragma unroll
        for (int s = 0; s < 2; s++) {
            int r0 = (wr * 32 + s * 16 + quad) * AS_U;
            int r8 = (wr * 32 + s * 16 + quad + 8) * AS_U;
            a[s][0] = AsU[r0 + ko + tq];
            a[s][1] = AsU[r8 + ko + tq];
            a[s][2] = AsU[r0 + ko + tq + 4];
            a[s][3] = AsU[r8 + ko + tq + 4];
        }
        uint32_t b[8][2];
#pragma unroll
        for (int nt = 0; nt < 8; nt++) {
            int n = (wc * 64 + nt * 8 + quad) * WT_U;
            b[nt][0] = WtU[n + ko + tq];
            b[nt][1] = WtU[n + ko + tq + 4];
        }
#pragma unroll
        for (int s = 0; s < 2; s++)
#pragma unroll
            for (int nt = 0; nt < 8; nt++)
                MMA_F16(acc[s][nt], a[s], b[nt]);
    }

    const int colBase = wc * 64;
#pragma unroll
    for (int nt = 0; nt < 8; nt++) {
        int col = colBase + nt * 8 + 2 * tq;
        float2 bb = *reinterpret_cast<const float2*>(bias + col);
#pragma unroll
        for (int s = 0; s < 2; s++) {
            int r0 = rowBase + wr * 32 + s * 16 + quad;
            if (r0 < N_NODES) {
                float2 o;
                o.x = fmaxf(acc[s][nt][0] + bb.x, 0.f);
                o.y = fmaxf(acc[s][nt][1] + bb.y, 0.f);
                out2[r0 * 64 + (col >> 1)] = o;
            }
            if (r0 + 8 < N_NODES) {
                float2 o;
                o.x = fmaxf(acc[s][nt][2] + bb.x, 0.f);
                o.y = fmaxf(acc[s][nt][3] + bb.y, 0.f);
                out2[(r0 + 8) * 64 + (col >> 1)] = o;
            }
        }
    }
}

// ---------------------------------------------------------------------------
// Inputs: x [N,D] f32, source [E] i32, target [E] i32, W [D,U] f32, b [U] f32
// ---------------------------------------------------------------------------
extern "C" void kernel_launch(void* const* d_in, const int* in_sizes, int n_in,
                              void* d_out, int out_size) {
    const float4* x   = (const float4*)d_in[0];
    const int*    src = (const int*)d_in[1];
    const int*    tgt = (const int*)d_in[2];
    const float4* W4  = (const float4*)d_in[3];
    const float*  b   = (const float*)d_in[4];
    float2* out2 = (float2*)d_out;

    cudaFuncSetAttribute(gemm_kernel,
                         cudaFuncAttributeMaxDynamicSharedMemorySize, GEMM_SMEM);

    zero_kernel<<<64, 256>>>();
    histconv_kernel<<<HIST_BLKS + CONV_BLKS, 256>>>(src, tgt, x);
    chunk_kernel<<<(N_NODES + 255) / 256, 256>>>();
    sort_kernel<<<(SORT_T + 255) / 256, 256>>>(src, tgt);
    gather_kernel<<<(N_NODES * 32 + 255) / 256, 256>>>();
    gemm_kernel<<<(N_NODES + 127) / 128, 256, GEMM_SMEM>>>(W4, b, out2);
}

// round 8
// speedup vs baseline: 1.0813x; 1.0813x over previous
#include <cuda_runtime.h>
#include <cuda_fp16.h>
#include <cstdint>

#define N_NODES 50000
#define D_FEAT  128
#define N_EDGES 800000

// Scratch (__device__ globals — allocation-free rule)
__device__ uint4  g_xh[N_NODES * 16];       // 12.8 MB fp16(x), unscaled
__device__ uint4  g_ph[N_NODES * 16];       // 12.8 MB fp16 pooled
__device__ int    g_hist_out[N_NODES];
__device__ int    g_hist_in[N_NODES];
__device__ int    g_start[N_NODES];
__device__ int    g_rank[N_EDGES];          // edge rank within its target group
__device__ int    g_sorted_src[N_EDGES];
__device__ float  g_sscale[N_NODES];
__device__ int    g_counter;

// ---------------------------------------------------------------------------
// K0: zero histograms + counter (vectorized)
// ---------------------------------------------------------------------------
__global__ void zero_kernel() {
    int i = blockIdx.x * blockDim.x + threadIdx.x;
    const int N4 = (N_NODES + 3) / 4;
    int stride = gridDim.x * blockDim.x;
    for (int j = i; j < N4; j += stride) {
        reinterpret_cast<int4*>(g_hist_out)[j] = make_int4(0, 0, 0, 0);
        reinterpret_cast<int4*>(g_hist_in)[j]  = make_int4(0, 0, 0, 0);
    }
    if (i == 0) g_counter = 0;
}

// ---------------------------------------------------------------------------
// K1 FUSED: hist+rank (8 edges/thread) + convert x->fp16 (independent).
// The in-degree atomicAdd's RETURN VALUE is the edge's rank within its
// target group — recorded so the later placement needs no atomics at all.
// Hist blocks first (critical path); DRAM-bound convert rides underneath.
// ---------------------------------------------------------------------------
#define HIST_T    (N_EDGES / 8)                      // 100000 threads
#define HIST_BLKS ((HIST_T + 255) / 256)             // 391
#define CONV_T    (N_NODES * 16 / 2)                 // 400000 threads
#define CONV_BLKS ((CONV_T + 255) / 256)             // 1563

__global__ __launch_bounds__(256) void histconv_kernel(
        const int* __restrict__ src,
        const int* __restrict__ tgt,
        const float4* __restrict__ x) {
    if (blockIdx.x < HIST_BLKS) {
        int t = blockIdx.x * 256 + threadIdx.x;
        if (t >= HIST_T) return;
        int sv[8], tg[8], rk[8];
#pragma unroll
        for (int u = 0; u < 8; u++) {
            sv[u] = __ldg(&src[t + u * HIST_T]);
            tg[u] = __ldg(&tgt[t + u * HIST_T]);
        }
#pragma unroll
        for (int u = 0; u < 8; u++) rk[u] = atomicAdd(&g_hist_in[tg[u]], 1);
#pragma unroll
        for (int u = 0; u < 8; u++) atomicAdd(&g_hist_out[sv[u]], 1);
#pragma unroll
        for (int u = 0; u < 8; u++) g_rank[t + u * HIST_T] = rk[u];
    } else {
        int i = (blockIdx.x - HIST_BLKS) * 256 + threadIdx.x;
        if (i >= CONV_T) return;
#pragma unroll
        for (int u = 0; u < 2; u++) {
            int idx = i + u * CONV_T;              // uint4 index (8 halfs)
            float4 v0 = __ldg(&x[2 * idx]);
            float4 v1 = __ldg(&x[2 * idx + 1]);
            __half2 h0 = __floats2half2_rn(v0.x, v0.y);
            __half2 h1 = __floats2half2_rn(v0.z, v0.w);
            __half2 h2 = __floats2half2_rn(v1.x, v1.y);
            __half2 h3 = __floats2half2_rn(v1.z, v1.w);
            uint4 p;
            p.x = *reinterpret_cast<uint32_t*>(&h0);
            p.y = *reinterpret_cast<uint32_t*>(&h1);
            p.z = *reinterpret_cast<uint32_t*>(&h2);
            p.w = *reinterpret_cast<uint32_t*>(&h3);
            g_xh[idx] = p;
        }
    }
}

// ---------------------------------------------------------------------------
// K2: chunk assignment (warp-aggregated global counter; order irrelevant)
// ---------------------------------------------------------------------------
__global__ void chunk_kernel() {
    int i    = blockIdx.x * blockDim.x + threadIdx.x;
    int lane = threadIdx.x & 31;
    int deg  = (i < N_NODES) ? g_hist_in[i] : 0;

    int incl = deg;
#pragma unroll
    for (int o = 1; o < 32; o <<= 1) {
        int n = __shfl_up_sync(0xFFFFFFFFu, incl, o);
        if (lane >= o) incl += n;
    }
    int total = __shfl_sync(0xFFFFFFFFu, incl, 31);
    int base = 0;
    if (lane == 31) base = atomicAdd(&g_counter, total);
    base = __shfl_sync(0xFFFFFFFFu, base, 31);

    if (i < N_NODES) {
        g_start[i]  = base + incl - deg;
        g_sscale[i] = rsqrtf(fmaxf((float)g_hist_out[i], 1.0f));
    }
}

// ---------------------------------------------------------------------------
// K3: placement — NO atomics. pos = start[tgt] + rank, plain scattered store.
// 8 edges/thread.
// ---------------------------------------------------------------------------
#define PLACE_T (N_EDGES / 8)

__global__ __launch_bounds__(256) void place_kernel(
        const int* __restrict__ src,
        const int* __restrict__ tgt) {
    int t = blockIdx.x * 256 + threadIdx.x;
    if (t >= PLACE_T) return;
    int tg[8], sv[8], rk[8], st[8];
#pragma unroll
    for (int u = 0; u < 8; u++) {
        tg[u] = __ldg(&tgt[t + u * PLACE_T]);
        sv[u] = __ldg(&src[t + u * PLACE_T]);
        rk[u] = __ldg(&g_rank[t + u * PLACE_T]);
    }
#pragma unroll
    for (int u = 0; u < 8; u++) st[u] = __ldg(&g_start[tg[u]]);
#pragma unroll
    for (int u = 0; u < 8; u++) g_sorted_src[st[u] + rk[u]] = sv[u];
}

// ---------------------------------------------------------------------------
// K4: gather. One warp per target node; half-warp per edge row (lane owns
// uint4 = 8 halfs) -> 2 edges/iter. Sender scale applied per edge (FMA);
// fp32 accumulate, shfl-combine halves, fp16 row written once.
// ---------------------------------------------------------------------------
__global__ __launch_bounds__(256) void gather_kernel() {
    int t    = (blockIdx.x * blockDim.x + threadIdx.x) >> 5;
    int lane = threadIdx.x & 31;
    if (t >= N_NODES) return;

    const int half = lane >> 4;
    const int fl   = lane & 15;

    int start = __ldg(&g_start[t]);
    int deg   = __ldg(&g_hist_in[t]);
    int end   = start + deg;

    float acc[8];
#pragma unroll
    for (int f = 0; f < 8; f++) acc[f] = 0.f;

    int j = start;
#pragma unroll 2
    for (; j + 1 < end; j += 2) {
        int   s  = __ldg(&g_sorted_src[j + half]);
        float sc = __ldg(&g_sscale[s]);
        uint4 e  = __ldg(&g_xh[s * 16 + fl]);
        const __half2* h = reinterpret_cast<const __half2*>(&e);
#pragma unroll
        for (int q = 0; q < 4; q++) {
            float2 f2 = __half22float2(h[q]);
            acc[2 * q]     = fmaf(sc, f2.x, acc[2 * q]);
            acc[2 * q + 1] = fmaf(sc, f2.y, acc[2 * q + 1]);
        }
    }
    if (j < end && half == 0) {
        int   s  = __ldg(&g_sorted_src[j]);
        float sc = __ldg(&g_sscale[s]);
        uint4 e  = __ldg(&g_xh[s * 16 + fl]);
        const __half2* h = reinterpret_cast<const __half2*>(&e);
#pragma unroll
        for (int q = 0; q < 4; q++) {
            float2 f2 = __half22float2(h[q]);
            acc[2 * q]     = fmaf(sc, f2.x, acc[2 * q]);
            acc[2 * q + 1] = fmaf(sc, f2.y, acc[2 * q + 1]);
        }
    }

#pragma unroll
    for (int f = 0; f < 8; f++)
        acc[f] += __shfl_down_sync(0xFFFFFFFFu, acc[f], 16);

    if (half == 0) {
        float rsc = rsqrtf(fmaxf((float)deg, 1.0f));
        __half2 h0 = __floats2half2_rn(acc[0] * rsc, acc[1] * rsc);
        __half2 h1 = __floats2half2_rn(acc[2] * rsc, acc[3] * rsc);
        __half2 h2 = __floats2half2_rn(acc[4] * rsc, acc[5] * rsc);
        __half2 h3 = __floats2half2_rn(acc[6] * rsc, acc[7] * rsc);
        uint4 p;
        p.x = *reinterpret_cast<uint32_t*>(&h0);
        p.y = *reinterpret_cast<uint32_t*>(&h1);
        p.z = *reinterpret_cast<uint32_t*>(&h2);
        p.w = *reinterpret_cast<uint32_t*>(&h3);
        g_ph[t * 16 + fl] = p;
    }
}

// ---------------------------------------------------------------------------
// K5: out = relu( pooled @ W + b ), fp16 mma.m16n8k16, fp32 accumulate.
// 256 thr, 128x128 tile, K=128 smem-resident, warp tile 32x64.
// ---------------------------------------------------------------------------
#define AS_U 68
#define WT_U 68
#define GEMM_SMEM ((128 * AS_U + 128 * WT_U) * 4)

#define MMA_F16(c, a, b)                                                      \
    asm volatile(                                                             \
        "mma.sync.aligned.m16n8k16.row.col.f32.f16.f16.f32 "                  \
        "{%0,%1,%2,%3},{%4,%5,%6,%7},{%8,%9},{%0,%1,%2,%3};"                  \
        : "+f"(c[0]), "+f"(c[1]), "+f"(c[2]), "+f"(c[3])                      \
        : "r"(a[0]), "r"(a[1]), "r"(a[2]), "r"(a[3]), "r"(b[0]), "r"(b[1]))

__global__ __launch_bounds__(256, 2) void gemm_kernel(
        const float4* __restrict__ W4,    // [128][32] float4 (k, j/4)
        const float*  __restrict__ bias,  // [128]
        float2* __restrict__ out2) {      // [N_NODES][64]
    extern __shared__ uint32_t smemU[];
    uint32_t* AsU = smemU;                 // [128][AS_U] half2 (row, k/2)
    uint32_t* WtU = smemU + 128 * AS_U;    // [128][WT_U] half2 (n,  k/2)
    __half*   WtH = reinterpret_cast<__half*>(WtU);

    const int tid  = threadIdx.x;
    const int lane = tid & 31;
    const int w    = tid >> 5;
    const int quad = lane >> 2;
    const int tq   = lane & 3;
    const int wr   = w & 3;
    const int wc   = w >> 2;
    const int rowBase = blockIdx.x * 128;

#pragma unroll
    for (int p = 0; p < 8; p++) {
        int idx = p * 256 + tid;          // 0..2047
        int r = idx >> 4, c = idx & 15;
        uint4 v = make_uint4(0u, 0u, 0u, 0u);
        if (rowBase + r < N_NODES) v = g_ph[(rowBase + r) * 16 + c];
        *reinterpret_cast<uint4*>(&AsU[r * AS_U + c * 4]) = v;
    }
#pragma unroll
    for (int p = 0; p < 16; p++) {
        int idx = p * 256 + tid;          // 0..4095
        int k = idx >> 5, c = idx & 31;
        float4 v = __ldg(&W4[idx]);
        WtH[(4 * c + 0) * (2 * WT_U) + k] = __float2half_rn(v.x);
        WtH[(4 * c + 1) * (2 * WT_U) + k] = __float2half_rn(v.y);
        WtH[(4 * c + 2) * (2 * WT_U) + k] = __float2half_rn(v.z);
        WtH[(4 * c + 3) * (2 * WT_U) + k] = __float2half_rn(v.w);
    }
    __syncthreads();

    float acc[2][8][4];
#pragma unroll
    for (int s = 0; s < 2; s++)
#pragma unroll
        for (int nt = 0; nt < 8; nt++)
#pragma unroll
            for (int j = 0; j < 4; j++) acc[s][nt][j] = 0.f;

#pragma unroll
    for (int kt = 0; kt < 8; kt++) {
        const int ko = kt * 8;
        uint32_t a[2][4];
#pragma unroll
        for (int s = 0; s < 2; s++) {
            int r0 = (wr * 32 + s * 16 + quad) * AS_U;
            int r8 = (wr * 32 + s * 16 + quad + 8) * AS_U;
            a[s][0] = AsU[r0 + ko + tq];
            a[s][1] = AsU[r8 + ko + tq];
            a[s][2] = AsU[r0 + ko + tq + 4];
            a[s][3] = AsU[r8 + ko + tq + 4];
        }
        uint32_t b[8][2];
#pragma unroll
        for (int nt = 0; nt < 8; nt++) {
            int n = (wc * 64 + nt * 8 + quad) * WT_U;
            b[nt][0] = WtU[n + ko + tq];
            b[nt][1] = WtU[n + ko + tq + 4];
        }
#pragma unroll
        for (int s = 0; s < 2; s++)
#pragma unroll
            for (int nt = 0; nt < 8; nt++)
                MMA_F16(acc[s][nt], a[s], b[nt]);
    }

    const int colBase = wc * 64;
#pragma unroll
    for (int nt = 0; nt < 8; nt++) {
        int col = colBase + nt * 8 + 2 * tq;
        float2 bb = *reinterpret_cast<const float2*>(bias + col);
#pragma unroll
        for (int s = 0; s < 2; s++) {
            int r0 = rowBase + wr * 32 + s * 16 + quad;
            if (r0 < N_NODES) {
                float2 o;
                o.x = fmaxf(acc[s][nt][0] + bb.x, 0.f);
                o.y = fmaxf(acc[s][nt][1] + bb.y, 0.f);
                out2[r0 * 64 + (col >> 1)] = o;
            }
            if (r0 + 8 < N_NODES) {
                float2 o;
                o.x = fmaxf(acc[s][nt][2] + bb.x, 0.f);
                o.y = fmaxf(acc[s][nt][3] + bb.y, 0.f);
                out2[(r0 + 8) * 64 + (col >> 1)] = o;
            }
        }
    }
}

// ---------------------------------------------------------------------------
// Inputs: x [N,D] f32, source [E] i32, target [E] i32, W [D,U] f32, b [U] f32
// ---------------------------------------------------------------------------
extern "C" void kernel_launch(void* const* d_in, const int* in_sizes, int n_in,
                              void* d_out, int out_size) {
    const float4* x   = (const float4*)d_in[0];
    const int*    src = (const int*)d_in[1];
    const int*    tgt = (const int*)d_in[2];
    const float4* W4  = (const float4*)d_in[3];
    const float*  b   = (const float*)d_in[4];
    float2* out2 = (float2*)d_out;

    cudaFuncSetAttribute(gemm_kernel,
                         cudaFuncAttributeMaxDynamicSharedMemorySize, GEMM_SMEM);

    zero_kernel<<<64, 256>>>();
    histconv_kernel<<<HIST_BLKS + CONV_BLKS, 256>>>(src, tgt, x);
    chunk_kernel<<<(N_NODES + 255) / 256, 256>>>();
    place_kernel<<<(PLACE_T + 255) / 256, 256>>>(src, tgt);
    gather_kernel<<<(N_NODES * 32 + 255) / 256, 256>>>();
    gemm_kernel<<<(N_NODES + 127) / 128, 256, GEMM_SMEM>>>(W4, b, out2);
}